// round 2
// baseline (speedup 1.0000x reference)
#include <cuda_runtime.h>

#define HH 4096
#define WW 4096
// 512 threads per image row, 8 pixels per thread

__global__ __launch_bounds__(256) void nms_kernel(
    const float* __restrict__ img,
    const float* __restrict__ theta,
    float* __restrict__ out)
{
    int idx = blockIdx.x * blockDim.x + threadIdx.x;   // 0 .. HH*512-1
    int h  = idx >> 9;             // row
    int w0 = (idx & 511) << 3;     // starting column (multiple of 8)
    long base = (long)h * WW + w0;

    const float4 zero4 = make_float4(0.f, 0.f, 0.f, 0.f);
    if (h == 0 || h == HH - 1) {
        reinterpret_cast<float4*>(out + base)[0] = zero4;
        reinterpret_cast<float4*>(out + base)[1] = zero4;
        return;
    }

    // ---- vector loads: 8 x LDG.128 ----
    const float4 t0 = __ldg(reinterpret_cast<const float4*>(theta + base));
    const float4 t1 = __ldg(reinterpret_cast<const float4*>(theta + base + 4));
    const float4 c0 = __ldg(reinterpret_cast<const float4*>(img + base));
    const float4 c1 = __ldg(reinterpret_cast<const float4*>(img + base + 4));
    const float4 u0 = __ldg(reinterpret_cast<const float4*>(img + base - WW));
    const float4 u1 = __ldg(reinterpret_cast<const float4*>(img + base - WW + 4));
    const float4 d0 = __ldg(reinterpret_cast<const float4*>(img + base + WW));
    const float4 d1 = __ldg(reinterpret_cast<const float4*>(img + base + WW + 4));

    // ---- halo scalars (clamped corners are never actually used: borders zeroed) ----
    long uli = base - WW - 1; if (uli < 0) uli = 0;
    long dri = base + WW + 8; if (dri >= (long)HH * WW) dri = (long)HH * WW - 1;

    const float lft = __ldg(img + base - 1);
    const float rgt = __ldg(img + base + 8);
    const float ul  = __ldg(img + uli);
    const float ur  = __ldg(img + base - WW + 8);
    const float dl  = __ldg(img + base + WW - 1);
    const float dr  = __ldg(img + dri);

    // column j of these arrays = image column (w0 - 1 + j)
    float row[10] = { lft, c0.x, c0.y, c0.z, c0.w, c1.x, c1.y, c1.z, c1.w, rgt };
    float uu [10] = { ul,  u0.x, u0.y, u0.z, u0.w, u1.x, u1.y, u1.z, u1.w, ur  };
    float dn [10] = { dl,  d0.x, d0.y, d0.z, d0.w, d1.x, d1.y, d1.z, d1.w, dr  };
    float th [8]  = { t0.x, t0.y, t0.z, t0.w, t1.x, t1.y, t1.z, t1.w };
    float o[8];

    const float RCP45 = 1.0f / 45.0f;   // constant-folded to RN(1/45)

    #pragma unroll
    for (int i = 0; i < 8; i++) {
        // deg = theta * f32(180/pi); single +180 if negative (matches reference)
        float deg = __fmul_rn(th[i], 57.29577951308232f);
        if (deg < 0.f) deg = __fadd_rn(deg, 180.f);

        // correctly-rounded deg/45 (Markstein: mul + 2 fma, bit-exact vs RN divide)
        float q0 = __fmul_rn(deg, RCP45);
        float rr = __fmaf_rn(-45.f, q0, deg);
        float qf = __fmaf_rn(rr, RCP45, q0);
        int   k  = __float2int_rn(qf);      // F2I.RNI = round half to even = jnp.round

        // k: 0 or 4 -> 0/180 deg; 1 -> 45; 2 -> 90; anything else -> 135 branch
        float a, b;
        if (k == 0 || k == 4) { a = row[i + 2]; b = row[i];     }
        else if (k == 1)      { a = dn [i + 2]; b = uu[i];      }
        else if (k == 2)      { a = dn [i + 1]; b = uu[i + 1];  }
        else                  { a = dn [i];     b = uu[i + 2];  }

        float cc = row[i + 1];
        o[i] = (cc >= fmaxf(a, b)) ? cc : 0.f;
    }

    // left / right image borders
    if (w0 == 0)       o[0] = 0.f;
    if (w0 == WW - 8)  o[7] = 0.f;

    reinterpret_cast<float4*>(out + base)[0] = make_float4(o[0], o[1], o[2], o[3]);
    reinterpret_cast<float4*>(out + base)[1] = make_float4(o[4], o[5], o[6], o[7]);
}

extern "C" void kernel_launch(void* const* d_in, const int* in_sizes, int n_in,
                              void* d_out, int out_size)
{
    const float* img   = (const float*)d_in[0];
    const float* theta = (const float*)d_in[1];
    float*       out   = (float*)d_out;

    const int n_threads = HH * (WW / 8);   // 2,097,152
    const int block     = 256;
    const int grid      = n_threads / block;  // 8192
    nms_kernel<<<grid, block>>>(img, theta, out);
}